// round 17
// baseline (speedup 1.0000x reference)
#include <cuda_runtime.h>
#include <cuda_fp16.h>
#include <math.h>
#include <stdint.h>

#define B       8192
#define INP     64
#define HID     1024
#define KA      1088
#define NG      4096          // 4 gates * HID, interleaved n = j*4 + g
#define OMID    128
#define MAX_IT  8

#define BM 256
#define BN 128
#define CHUNKS 16             // state K chunks of 64
#define NTILES (NG / BN)      // 32
#define G_STAGE 49152         // A 32K + W 16K (single fp16 W)
#define SMEM_DYN_G 197632     // 4 stages 196608 (C tile 135168 overlays stages 0-2)
#define CSTRIDE 132

// head geometry: 64 rows/CTA, 1-term fp16 W1, 4-stage pipeline
#define HBM 64
#define NH_PAD 144
#define H_CHUNKS 16
#define H_STAGE 26624         // A 8K + W 18K
#define SMEM_DYN_H 107520     // 4 stages 106496 (C tile 37888 overlays)
#define HCS 148

// ---------------- device scratch ---------------------------------------------
__device__ __half g_A0[B * HID];            // state ping-pong (single fp16)
__device__ __half g_A1[B * HID];
__device__ __half g_x[B * INP];
__device__ float  g_cell[B * HID];
__device__ __half g_Wimg[NTILES * CHUNKS * 8192];    // state-K image, single fp16
__device__ __half g_Wx_img[NTILES * 16384];          // x-K image: [T][hi|lo] (2-term)
__device__ __half g_W1img[H_CHUNKS * NH_PAD * 64];   // head image, single fp16
__device__ float  g_gx[(size_t)B * NG];              // x @ Wx^T + bias (fp32)
__device__ float  g_bias[NG];
__device__ float  g_b1h[OMID + 2];
__device__ float  g_psum[B];
__device__ int    g_mapA[B];
__device__ int    g_mapB[B];
__device__ int    g_cnt[MAX_IT + 1];

__device__ __forceinline__ float sigf(float z) { return 1.0f / (1.0f + expf(-z)); }

// ---------------- PTX helpers (base ISA only) ---------------------------------
__device__ __forceinline__ uint32_t smem_u32(const void* p) {
    uint32_t a;
    asm("{ .reg .u64 t; cvta.to.shared.u64 t, %1; cvt.u32.u64 %0, t; }" : "=r"(a) : "l"(p));
    return a;
}
__device__ __forceinline__ void cp16(uint32_t dst, const void* src) {
    asm volatile("cp.async.cg.shared.global [%0], [%1], 16;" :: "r"(dst), "l"(src));
}
#define CP_COMMIT() asm volatile("cp.async.commit_group;" ::: "memory")
#define CP_WAIT(n)  asm volatile("cp.async.wait_group %0;" :: "n"(n) : "memory")

#define LDM4(r, addr) \
    asm volatile("ldmatrix.sync.aligned.m8n8.x4.shared.b16 {%0,%1,%2,%3}, [%4];" \
        : "=r"((r)[0]), "=r"((r)[1]), "=r"((r)[2]), "=r"((r)[3]) : "r"(addr))

#define MMA16816(acc, a, b0v, b1v) \
    asm volatile("mma.sync.aligned.m16n8k16.row.col.f32.f16.f16.f32 " \
        "{%0,%1,%2,%3}, {%4,%5,%6,%7}, {%8,%9}, {%0,%1,%2,%3};" \
        : "+f"((acc)[0]), "+f"((acc)[1]), "+f"((acc)[2]), "+f"((acc)[3]) \
        : "r"((a)[0]), "r"((a)[1]), "r"((a)[2]), "r"((a)[3]), "r"(b0v), "r"(b1v))

__device__ __forceinline__ unsigned short hfu(__half v) {
    return *reinterpret_cast<unsigned short*>(&v);
}
__device__ __forceinline__ uint4 pack8h(const float* w) {
    unsigned short hs[8];
#pragma unroll
    for (int u = 0; u < 8; u++) hs[u] = hfu(__float2half_rn(w[u]));
    return make_uint4((uint32_t)hs[0] | ((uint32_t)hs[1] << 16),
                      (uint32_t)hs[2] | ((uint32_t)hs[3] << 16),
                      (uint32_t)hs[4] | ((uint32_t)hs[5] << 16),
                      (uint32_t)hs[6] | ((uint32_t)hs[7] << 16));
}
__device__ __forceinline__ void split8h(const float* w, uint4& hv, uint4& lv) {
    unsigned short hs[8], ls[8];
#pragma unroll
    for (int u = 0; u < 8; u++) {
        __half hi = __float2half_rn(w[u]);
        __half lo = __float2half_rn(w[u] - __half2float(hi));
        hs[u] = hfu(hi); ls[u] = hfu(lo);
    }
    hv = make_uint4((uint32_t)hs[0] | ((uint32_t)hs[1] << 16),
                    (uint32_t)hs[2] | ((uint32_t)hs[3] << 16),
                    (uint32_t)hs[4] | ((uint32_t)hs[5] << 16),
                    (uint32_t)hs[6] | ((uint32_t)hs[7] << 16));
    lv = make_uint4((uint32_t)ls[0] | ((uint32_t)ls[1] << 16),
                    (uint32_t)ls[2] | ((uint32_t)ls[3] << 16),
                    (uint32_t)ls[4] | ((uint32_t)ls[5] << 16),
                    (uint32_t)ls[6] | ((uint32_t)ls[7] << 16));
}

// ---------------- init (split in two so ncu -s 5 lands on gates t1) -----------
__global__ void k_initA(const float* __restrict__ x) {
    const int row = blockIdx.x;
    const int t = threadIdx.x;                 // 64 threads
    g_x[row * INP + t] = __float2half_rn(x[row * INP + t]);
}
__global__ void k_initB(float* __restrict__ out) {
    const int i = blockIdx.x * blockDim.x + threadIdx.x;
    if (i < B) {
        g_psum[i] = 0.0f;
        g_mapA[i] = i;
        out[i] = 0.0f;
    }
    if (i <= MAX_IT) g_cnt[i] = (i == 0) ? B : 0;
}

// ---------------- pack weights ------------------------------------------------
__global__ void k_pack(
    const float* __restrict__ Wxi, const float* __restrict__ Whi,
    const float* __restrict__ bxi, const float* __restrict__ bhi,
    const float* __restrict__ Wxf, const float* __restrict__ Whf,
    const float* __restrict__ bxf, const float* __restrict__ bhf,
    const float* __restrict__ Wxc, const float* __restrict__ Whc,
    const float* __restrict__ bxc, const float* __restrict__ bhc,
    const float* __restrict__ Wxo, const float* __restrict__ Who,
    const float* __restrict__ bxo, const float* __restrict__ bho,
    const float* __restrict__ W1,  const float* __restrict__ b1,
    const float* __restrict__ Whalt, const float* __restrict__ bhalt)
{
    int idx = blockIdx.x * blockDim.x + threadIdx.x;
    if (idx < NG * (KA / 8)) {
        const int n = idx / (KA / 8);
        const int kb = idx % (KA / 8);
        const int g = n & 3;
        const int j = n >> 2;
        const float* Wx = (g == 0) ? Wxi : (g == 1) ? Wxf : (g == 2) ? Wxc : Wxo;
        const float* Wh = (g == 0) ? Whi : (g == 1) ? Whf : (g == 2) ? Whc : Who;
        float w[8];
        if (kb < 8) {
            const float* s = Wx + j * INP + kb * 8;
#pragma unroll
            for (int u = 0; u < 8; u++) w[u] = s[u];
        } else {
            const float* s = Wh + j * HID + (kb - 8) * 8;
#pragma unroll
            for (int u = 0; u < 8; u++) w[u] = s[u];
        }
        const int T = n >> 7, nr = n & 127;
        if (kb < 8) {   // x-part image: 2-term (hi|lo)
            uint4 hv, lv;
            split8h(w, hv, lv);
            const unsigned byte = ((unsigned)(nr * 128 + kb * 16)) ^ (((unsigned)(nr & 7)) << 4);
            const unsigned off_b = (unsigned)(T * 32768) + byte;
            *(uint4*)((char*)g_Wx_img + off_b) = hv;
            *(uint4*)((char*)g_Wx_img + off_b + 16384) = lv;
        } else {        // state-part image: single fp16
            const int C = (kb - 8) >> 3, kq = (kb - 8) & 7;
            const unsigned byte = ((unsigned)(nr * 128 + kq * 16)) ^ (((unsigned)(nr & 7)) << 4);
            const unsigned off_b = (unsigned)((T * CHUNKS + C) * 16384) + byte;
            *(uint4*)((char*)g_Wimg + off_b) = pack8h(w);
        }
        return;
    }
    idx -= NG * (KA / 8);
    if (idx < NH_PAD * (HID / 8)) {            // head W1/Whalt image (single fp16)
        const int n = idx / (HID / 8);
        const int kb = idx % (HID / 8);
        float w[8];
#pragma unroll
        for (int u = 0; u < 8; u++) {
            const int k = kb * 8 + u;
            w[u] = (n < OMID) ? W1[n * HID + k] : (n == OMID ? Whalt[k] : 0.0f);
        }
        const int C = kb >> 3;
        const unsigned byte = ((unsigned)(n * 128 + (kb & 7) * 16)) ^ (((unsigned)(n & 7)) << 4);
        const unsigned off_b = (unsigned)(C * 18432) + byte;
        *(uint4*)((char*)g_W1img + off_b) = pack8h(w);
        return;
    }
    idx -= NH_PAD * (HID / 8);
    if (idx < NG) {
        const int g = idx & 3;
        const int j = idx >> 2;
        const float* bx = (g == 0) ? bxi : (g == 1) ? bxf : (g == 2) ? bxc : bxo;
        const float* bh = (g == 0) ? bhi : (g == 1) ? bhf : (g == 2) ? bhc : bho;
        g_bias[idx] = bx[j] + bh[j];
        return;
    }
    idx -= NG;
    if (idx < OMID) { g_b1h[idx] = b1[idx]; return; }
    idx -= OMID;
    if (idx == 0) g_b1h[OMID] = bhalt[0];
}

// ---------------- k_gx: gx = x @ Wx^T + bias (2-term) + fused t=0 LSTM --------
__global__ __launch_bounds__(256, 1) void k_gx() {
    extern __shared__ char smem[];
    const int m0 = blockIdx.y * BM;
    const int n0 = blockIdx.x * BN;
    const int tid = threadIdx.x;
    const int wrp = tid >> 5;
    const int lane = tid & 31;

    const uint32_t sb0 = smem_u32(smem);
    const uint32_t tiles = (sb0 + 1023) & ~1023u;
    char* tilesPtr = smem + (tiles - sb0);

    const int myrow = m0 + tid;
    const char* pA = (const char*)(g_x + (size_t)myrow * INP);
    const uint32_t aswz = (uint32_t)(tid & 7) << 4;
    const uint32_t aDstRow = (uint32_t)tid * 128;
    const char* pW = (const char*)g_Wx_img + (size_t)blockIdx.x * 32768;

    {
#pragma unroll
        for (int u = 0; u < 8; u++)
            cp16(tiles + aDstRow + (((uint32_t)(u * 16)) ^ aswz), pA + u * 16);
#pragma unroll
        for (int q = 0; q < 8; q++) {
            const uint32_t o = (uint32_t)(tid + q * 256) << 4;
            cp16(tiles + 32768 + o, pW + o);
        }
        CP_COMMIT();
    }

    const int wm = (wrp & 3) * 64;
    const int wn = (wrp >> 2) * 64;
    const uint32_t fswz = (uint32_t)(lane & 7) << 4;
    const uint32_t aRowOff = (uint32_t)(wm + (lane & 15)) * 128;
    const uint32_t aKsel = (uint32_t)(lane >> 4) * 16;
    const uint32_t bRowOff = (uint32_t)(wn + (lane & 7) + ((lane >> 4) << 3)) * 128;
    const uint32_t bKsel = (uint32_t)((lane >> 3) & 1) * 16;

    float acc[4][8][4];
#pragma unroll
    for (int mi = 0; mi < 4; mi++)
#pragma unroll
        for (int nj = 0; nj < 8; nj++)
#pragma unroll
            for (int e = 0; e < 4; e++) acc[mi][nj][e] = 0.0f;

    CP_WAIT(0);
    __syncthreads();
    {
        const uint32_t ahB = tiles + aRowOff;
        const uint32_t whB = tiles + 32768 + bRowOff;
        const uint32_t wlB = tiles + 49152 + bRowOff;
#pragma unroll
        for (int ks = 0; ks < 4; ks++) {
            const uint32_t ak = ((uint32_t)(ks * 32) + aKsel) ^ fswz;
            const uint32_t bk = ((uint32_t)(ks * 32) + bKsel) ^ fswz;
            uint32_t bh[4][4], bl[4][4];
#pragma unroll
            for (int ni = 0; ni < 4; ni++) {
                LDM4(bh[ni], whB + ni * 2048 + bk);
                LDM4(bl[ni], wlB + ni * 2048 + bk);
            }
#pragma unroll
            for (int mi = 0; mi < 4; mi++) {
                uint32_t ah[4];
                LDM4(ah, ahB + mi * 2048 + ak);
#pragma unroll
                for (int nj = 0; nj < 8; nj++) {
                    const int ni = nj >> 1, pr = (nj & 1) * 2;
                    MMA16816(acc[mi][nj], ah, bh[ni][pr], bh[ni][pr + 1]);
                    MMA16816(acc[mi][nj], ah, bl[ni][pr], bl[ni][pr + 1]);
                }
            }
        }
    }
    __syncthreads();

    float* C = (float*)tilesPtr;
    {
        const int r0 = wm + (lane >> 2);
        const int c0 = wn + 2 * (lane & 3);
#pragma unroll
        for (int mi = 0; mi < 4; mi++)
#pragma unroll
            for (int nj = 0; nj < 8; nj++) {
                float* p = C + (r0 + mi * 16) * CSTRIDE + c0 + nj * 8;
                p[0] = acc[mi][nj][0];
                p[1] = acc[mi][nj][1];
                p[8 * CSTRIDE]     = acc[mi][nj][2];
                p[8 * CSTRIDE + 1] = acc[mi][nj][3];
            }
    }
    __syncthreads();

    // ---- epilogue: store gx+bias AND t=0 LSTM pointwise (state=cell=0) ----
    {
        float* gxo = g_gx + (size_t)myrow * NG + n0;
        const float* Crow = C + tid * CSTRIDE;
        const float* bb = g_bias + n0;
        const int j0 = n0 >> 2;
        float* cellp = g_cell + (size_t)myrow * HID + j0;
        uint32_t sp[16];
#pragma unroll
        for (int u = 0; u < 32; u++) {
            float4 gv = *(const float4*)(Crow + u * 4);
            gv.x += bb[u * 4 + 0];
            gv.y += bb[u * 4 + 1];
            gv.z += bb[u * 4 + 2];
            gv.w += bb[u * 4 + 3];
            *(float4*)(gxo + u * 4) = gv;      // gx with bias folded in
            const float ig = sigf (gv.x);
            const float cg = tanhf(gv.z);
            const float og = sigf (gv.w);
            const float c2 = ig * cg;           // f*0 + i*c
            cellp[u] = c2;
            const float s = og * tanhf(c2);
            const uint32_t su = hfu(__float2half_rn(s));
            if (u & 1) sp[u >> 1] |= su << 16;
            else       sp[u >> 1] = su;
        }
        uint4* sh = (uint4*)(g_A1 + (size_t)myrow * HID + j0);
#pragma unroll
        for (int v = 0; v < 4; v++)
            sh[v] = make_uint4(sp[v * 4], sp[v * 4 + 1], sp[v * 4 + 2], sp[v * 4 + 3]);
    }
}

// ---------------- gates (t>=1): 512-thread 1-term fp16 GEMM, 4-stage ----------
__global__ __launch_bounds__(512, 1) void k_gates(int t) {
    extern __shared__ char smem[];
    __shared__ int sRow[BM];

    const int count = g_cnt[t];
    const int m0 = blockIdx.y * BM;
    if (m0 >= count) return;
    const int n0 = blockIdx.x * BN;
    const int tid = threadIdx.x;
    const int wrp = tid >> 5;          // 0..15
    const int lane = tid & 31;

    const uint32_t sb0 = smem_u32(smem);
    const uint32_t tiles = (sb0 + 1023) & ~1023u;
    char* tilesPtr = smem + (tiles - sb0);

    const int* map = (t & 1) ? g_mapB : g_mapA;
    if (tid < BM) sRow[tid] = map[min(m0 + tid, count - 1)];
    __syncthreads();

    const __half* Ain = (t & 1) ? g_A1 : g_A0;
    __half*       Aout = (t & 1) ? g_A0 : g_A1;

    // loader split: tid<256 -> A row tid; tid>=256 -> W lines
    const int arow = tid & 255;
    const int myrow = sRow[arow];
    const char* pA = (const char*)(Ain + (size_t)myrow * HID);
    const uint32_t aswz = (uint32_t)(arow & 7) << 4;
    const uint32_t aDstRow = (uint32_t)arow * 128;
    const char* pW = (const char*)g_Wimg + (size_t)blockIdx.x * (CHUNKS * 16384);
    const int wline = tid - 256;

    auto load_chunk = [&](int c, int stage) {
        const uint32_t tb = tiles + (uint32_t)stage * G_STAGE;
        if (tid < 256) {
            const char* sa = pA + c * 128;
#pragma unroll
            for (int u = 0; u < 8; u++)
                cp16(tb + aDstRow + (((uint32_t)(u * 16)) ^ aswz), sa + u * 16);
        } else {
            const char* wc = pW + c * 16384;
#pragma unroll
            for (int q = 0; q < 4; q++) {
                const uint32_t o = (uint32_t)(wline + q * 256) << 4;
                cp16(tb + 32768 + o, wc + o);
            }
        }
        CP_COMMIT();
    };

    // warp tiling: 4m x 4n warps, warp tile 64m x 32n
    const int wm = (wrp & 3) * 64;
    const int wn = (wrp >> 2) * 32;
    const uint32_t fswz = (uint32_t)(lane & 7) << 4;
    const uint32_t aRowOff = (uint32_t)(wm + (lane & 15)) * 128;
    const uint32_t aKsel = (uint32_t)(lane >> 4) * 16;
    const uint32_t bRowOff = (uint32_t)(wn + (lane & 7) + ((lane >> 4) << 3)) * 128;
    const uint32_t bKsel = (uint32_t)((lane >> 3) & 1) * 16;

    float acc[4][4][4];
#pragma unroll
    for (int mi = 0; mi < 4; mi++)
#pragma unroll
        for (int nj = 0; nj < 4; nj++)
#pragma unroll
            for (int e = 0; e < 4; e++) acc[mi][nj][e] = 0.0f;

    // 4-stage pipeline
    load_chunk(0, 0);
    load_chunk(1, 1);
    load_chunk(2, 2);
    for (int c = 0; c < CHUNKS; c++) {
        const int stage = c & 3;
        if (c + 2 < CHUNKS)      { CP_WAIT(2); }
        else if (c + 1 < CHUNKS) { CP_WAIT(1); }
        else                     { CP_WAIT(0); }
        __syncthreads();
        if (c + 3 < CHUNKS) load_chunk(c + 3, (c + 3) & 3);

        const uint32_t tb = tiles + (uint32_t)stage * G_STAGE;
        const uint32_t ahB = tb + aRowOff;
        const uint32_t whB = tb + 32768 + bRowOff;

#pragma unroll
        for (int ks = 0; ks < 4; ks++) {
            const uint32_t ak = ((uint32_t)(ks * 32) + aKsel) ^ fswz;
            const uint32_t bk = ((uint32_t)(ks * 32) + bKsel) ^ fswz;
            uint32_t bh[2][4];
#pragma unroll
            for (int ni = 0; ni < 2; ni++)
                LDM4(bh[ni], whB + ni * 2048 + bk);
#pragma unroll
            for (int mi = 0; mi < 4; mi++) {
                uint32_t ah[4];
                LDM4(ah, ahB + mi * 2048 + ak);
#pragma unroll
                for (int nj = 0; nj < 4; nj++) {
                    const int ni = nj >> 1, pr = (nj & 1) * 2;
                    MMA16816(acc[mi][nj], ah, bh[ni][pr], bh[ni][pr + 1]);
                }
            }
        }
    }
    __syncthreads();

    float* C = (float*)tilesPtr;
    {
        const int r0 = wm + (lane >> 2);
        const int c0 = wn + 2 * (lane & 3);
#pragma unroll
        for (int mi = 0; mi < 4; mi++)
#pragma unroll
            for (int nj = 0; nj < 4; nj++) {
                float* p = C + (r0 + mi * 16) * CSTRIDE + c0 + nj * 8;
                p[0] = acc[mi][nj][0];
                p[1] = acc[mi][nj][1];
                p[8 * CSTRIDE]     = acc[mi][nj][2];
                p[8 * CSTRIDE + 1] = acc[mi][nj][3];
            }
    }
    __syncthreads();

    // ---- LSTM epilogue: thread = (row = tid&255, half = tid>>8), 16 units ----
    {
        const int row = tid & 255;
        const int hlf = tid >> 8;
        if (m0 + row < count) {
            const int rowg = sRow[row];
            const float* Crow = C + row * CSTRIDE + hlf * 64;
            const float* gxp = g_gx + (size_t)rowg * NG + n0 + hlf * 64;   // bias folded
            const int j0 = (n0 >> 2) + hlf * 16;
            float* cellp = g_cell + (size_t)rowg * HID + j0;
            uint32_t sp[8];
#pragma unroll
            for (int u = 0; u < 16; u++) {
                const float4 gv = *(const float4*)(Crow + u * 4);
                const float4 xv = *(const float4*)(gxp + u * 4);
                const float ig = sigf (gv.x + xv.x);
                const float fg = sigf (gv.y + xv.y);
                const float cg = tanhf(gv.z + xv.z);
                const float og = sigf (gv.w + xv.w);
                const float c2 = fg * cellp[u] + ig * cg;
                cellp[u] = c2;
                const float s = og * tanhf(c2);
                const uint32_t su = hfu(__float2half_rn(s));
                if (u & 1) sp[u >> 1] |= su << 16;
                else       sp[u >> 1] = su;
            }
            uint4* sh = (uint4*)(Aout + (size_t)rowg * HID + j0);
            sh[0] = make_uint4(sp[0], sp[1], sp[2], sp[3]);
            sh[1] = make_uint4(sp[4], sp[5], sp[6], sp[7]);
        }
    }
}

// ---------------- head: 64 rows/CTA, 128 thr, 1-term fp16 W1, 4-stage ---------
__global__ __launch_bounds__(128, 2) void k_head(int t,
                                                 const float* __restrict__ W2,
                                                 const float* __restrict__ b2,
                                                 float* __restrict__ out) {
    extern __shared__ char smem[];
    __shared__ int sRow[HBM];

    const int count = g_cnt[t];
    const int base = blockIdx.x * HBM;
    if (base >= count) return;
    const int tid = threadIdx.x;       // 128
    const int wrp = tid >> 5;          // 0..3
    const int lane = tid & 31;

    const uint32_t sb0 = smem_u32(smem);
    const uint32_t tiles = (sb0 + 1023) & ~1023u;
    char* tilesPtr = smem + (tiles - sb0);

    const int* map = (t & 1) ? g_mapB : g_mapA;
    int* map_next  = (t & 1) ? g_mapA : g_mapB;
    if (tid < HBM) sRow[tid] = map[min(base + tid, count - 1)];
    __syncthreads();

    // state after iter t: t even -> A1, t odd -> A0
    const __half* Astate = (t & 1) ? g_A0 : g_A1;

    const int arow = tid & 63;
    const int ahalf = tid >> 6;        // 0,1 -> 4 lines each
    const char* pA = (const char*)(Astate + (size_t)sRow[arow] * HID);
    const uint32_t aswz = (uint32_t)(arow & 7) << 4;
    const uint32_t aDstRow = (uint32_t)arow * 128;
    const char* pW = (const char*)g_W1img;

    auto load_chunk = [&](int c, int stage) {
        const uint32_t tb = tiles + (uint32_t)stage * H_STAGE;
        const char* src = pA + c * 128;
#pragma unroll
        for (int u = 0; u < 4; u++) {
            const int line = ahalf * 4 + u;
            cp16(tb + aDstRow + (((uint32_t)(line * 16)) ^ aswz), src + line * 16);
        }
        const char* w = pW + c * 18432;
#pragma unroll
        for (int q = 0; q < 9; q++) {          // 1152 lines = 9 * 128
            const uint32_t i = (uint32_t)(tid + q * 128);
            cp16(tb + 8192 + i * 16, w + (size_t)i * 16);
        }
        CP_COMMIT();
    };

    const int wm = wrp * 16;
    const uint32_t fswz = (uint32_t)(lane & 7) << 4;
    const uint32_t aRowOff = (uint32_t)(wm + (lane & 15)) * 128;
    const uint32_t aKsel = (uint32_t)(lane >> 4) * 16;
    const uint32_t bRowOff = (uint32_t)((lane & 7) + ((lane >> 4) << 3)) * 128;
    const uint32_t bKsel = (uint32_t)((lane >> 3) & 1) * 16;

    float acc[18][4];
#pragma unroll
    for (int nj = 0; nj < 18; nj++)
#pragma unroll
        for (int e = 0; e < 4; e++) acc[nj][e] = 0.0f;

    load_chunk(0, 0);
    load_chunk(1, 1);
    load_chunk(2, 2);
    for (int c = 0; c < H_CHUNKS; c++) {
        const int stage = c & 3;
        if (c + 2 < H_CHUNKS)      { CP_WAIT(2); }
        else if (c + 1 < H_CHUNKS) { CP_WAIT(1); }
        else                       { CP_WAIT(0); }
        __syncthreads();
        if (c + 3 < H_CHUNKS) load_chunk(c + 3, (c + 3) & 3);

        const uint32_t tb = tiles + (uint32_t)stage * H_STAGE;
        const uint32_t ahB = tb + aRowOff;
        const uint32_t whB = tb + 8192 + bRowOff;

#pragma unroll
        for (int ks = 0; ks < 4; ks++) {
            const uint32_t ak = ((uint32_t)(ks * 32) + aKsel) ^ fswz;
            const uint32_t bk = ((uint32_t)(ks * 32) + bKsel) ^ fswz;
            uint32_t ah[4], bh[9][4];
            LDM4(ah, ahB + ak);
#pragma unroll
            for (int ni = 0; ni < 9; ni++)
                LDM4(bh[ni], whB + ni * 2048 + bk);
#pragma unroll
            for (int nj = 0; nj < 18; nj++) {
                const int ni = nj >> 1, pr = (nj & 1) * 2;
                MMA16816(acc[nj], ah, bh[ni][pr], bh[ni][pr + 1]);
            }
        }
    }
    __syncthreads();

    float* C = (float*)tilesPtr;
    {
        const int r0 = wm + (lane >> 2);
        const int c0 = 2 * (lane & 3);
#pragma unroll
        for (int nj = 0; nj < 18; nj++) {
            float* p = C + r0 * HCS + c0 + nj * 8;
            p[0] = acc[nj][0];
            p[1] = acc[nj][1];
            p[8 * HCS]     = acc[nj][2];
            p[8 * HCS + 1] = acc[nj][3];
        }
    }
    __syncthreads();

    const float4 w2v = *(const float4*)(W2 + lane * 4);
    const float4 b1v = *(const float4*)(g_b1h + lane * 4);
    const float bhalt = g_b1h[OMID];

    for (int i = 0; i < 16; i++) {
        const int r = wm + i;
        const int mm = base + r;
        if (mm >= count) continue;
        const int rowg = sRow[r];

        const float4 mv = *(const float4*)&C[r * HCS + lane * 4];
        float acc2 = fmaxf(mv.x + b1v.x, 0.0f) * w2v.x
                   + fmaxf(mv.y + b1v.y, 0.0f) * w2v.y
                   + fmaxf(mv.z + b1v.z, 0.0f) * w2v.z
                   + fmaxf(mv.w + b1v.w, 0.0f) * w2v.w;
#pragma unroll
        for (int off = 16; off; off >>= 1)
            acc2 += __shfl_xor_sync(0xffffffffu, acc2, off);

        if (lane == 0) {
            const float o = sigf(acc2 + b2[0]);
            const float h = sigf(C[r * HCS + OMID] + bhalt);
            const float p = g_psum[rowg];
            const float pn = p + h;
            const bool fin = (pn >= 1.0f - 0.001f) || (t == MAX_IT - 1);
            const float hr = fin ? (1.0f - p) : h;
            out[rowg] += o * hr;
            g_psum[rowg] = fin ? 1.0f : pn;
            if (!fin) {
                int slot = atomicAdd(&g_cnt[t + 1], 1);
                map_next[slot] = rowg;
            }
        }
    }
}

// ---------------- launch ------------------------------------------------------
extern "C" void kernel_launch(void* const* d_in, const int* in_sizes, int n_in,
                              void* d_out, int out_size) {
    const float* x     = (const float*)d_in[0];
    const float* Wxi   = (const float*)d_in[1];
    const float* bxi   = (const float*)d_in[2];
    const float* Whi   = (const float*)d_in[3];
    const float* bhi   = (const float*)d_in[4];
    const float* Wxf   = (const float*)d_in[5];
    const float* bxf   = (const float*)d_in[6];
    const float* Whf   = (const float*)d_in[7];
    const float* bhf   = (const float*)d_in[8];
    const float* Wxc   = (const float*)d_in[9];
    const float* bxc   = (const float*)d_in[10];
    const float* Whc   = (const float*)d_in[11];
    const float* bhc   = (const float*)d_in[12];
    const float* Wxo   = (const float*)d_in[13];
    const float* bxo   = (const float*)d_in[14];
    const float* Who   = (const float*)d_in[15];
    const float* bho   = (const float*)d_in[16];
    const float* Whalt = (const float*)d_in[17];
    const float* bhalt = (const float*)d_in[18];
    const float* W1    = (const float*)d_in[19];
    const float* b1    = (const float*)d_in[20];
    const float* W2    = (const float*)d_in[21];
    const float* b2    = (const float*)d_in[22];
    float* out = (float*)d_out;

    cudaFuncSetAttribute(k_gates, cudaFuncAttributeMaxDynamicSharedMemorySize, SMEM_DYN_G);
    cudaFuncSetAttribute(k_gx,    cudaFuncAttributeMaxDynamicSharedMemorySize, 136192);
    cudaFuncSetAttribute(k_head,  cudaFuncAttributeMaxDynamicSharedMemorySize, SMEM_DYN_H);

    k_initA<<<B, INP>>>(x);                    // launch 0
    k_initB<<<(B + 255) / 256, 256>>>(out);    // launch 1

    const int tot = NG * (KA / 8) + NH_PAD * (HID / 8) + NG + OMID + 1;
    k_pack<<<(tot + 255) / 256, 256>>>(Wxi, Whi, bxi, bhi,     // launch 2
                                       Wxf, Whf, bxf, bhf,
                                       Wxc, Whc, bxc, bhc,
                                       Wxo, Who, bxo, bho,
                                       W1, b1, Whalt, bhalt);

    k_gx<<<dim3(NTILES, B / BM), 256, 136192>>>();             // launch 3
    k_head<<<B / HBM, 128, SMEM_DYN_H>>>(0, W2, b2, out);      // launch 4

    for (int t = 1; t < MAX_IT; t++) {
        k_gates<<<dim3(NTILES, B / BM), 512, SMEM_DYN_G>>>(t); // t=1 is launch 5 (ncu -s 5)
        k_head<<<B / HBM, 128, SMEM_DYN_H>>>(t, W2, b2, out);
    }
}